// round 7
// baseline (speedup 1.0000x reference)
#include <cuda_runtime.h>
#include <math.h>
#include <stdint.h>

// ---------------------------------------------------------------------------
// SoftMoE forward, tensor-core tf32 (m16n8k8, fp32 accum).
// Mainloop optimized: operands pre-rounded to tf32 wherever possible (feed raw
// bits, no cvt); A fragments via LDS.64 from a k-pair-permuted, bank-swizzled
// smem layout; expert stages batch-merged to M=256.
// Logits GEMM keeps the 3xTF32 split (fp32-grade) to protect argmax outputs.
// B=4, M=1024, D=768, E=16, P=64, F=3072.
// ---------------------------------------------------------------------------

namespace cfg {
constexpr int cB = 4, cM = 1024, cD = 768, cE = 16, cP = 64, cF = 3072;
constexpr int cEP = cE * cP;  // 1024
constexpr long long SZ_OUT  = (long long)cB * cM * cD;
constexpr long long SZ_PROB = (long long)cB * cM * cE;
constexpr long long SZ_TOP  = (long long)cB * cM;
constexpr long long SZ_HID  = (long long)cB * cE * cP * cF;
constexpr long long SZ_FULL = SZ_OUT + SZ_PROB + SZ_TOP + SZ_HID;
}
using namespace cfg;

// Scratch (allocation-free: __device__ globals).
__device__ float g_logits  [(size_t)cB * cM * cEP];
__device__ float g_dispatch[(size_t)cB * cM * cEP];
__device__ float g_combine [(size_t)cB * cM * cEP];
__device__ float g_mix     [(size_t)cB * cE * cP * cD];
__device__ float g_eout    [(size_t)cB * cE * cP * cD];
__device__ float g_xtf     [(size_t)cB * cM * cD];       // tf32-rounded x
__device__ float g_hid     [(size_t)cB * cE * cP * cF];  // tf32-rounded hidden

// ---------------------------------------------------------------------------
// PTX helpers
// ---------------------------------------------------------------------------
__device__ __forceinline__ void cp_async16(void* s, const void* g) {
    unsigned sa = (unsigned)__cvta_generic_to_shared(s);
    asm volatile("cp.async.ca.shared.global [%0], [%1], 16;\n" :: "r"(sa), "l"(g));
}
__device__ __forceinline__ void cp_async4(void* s, const void* g) {
    unsigned sa = (unsigned)__cvta_generic_to_shared(s);
    asm volatile("cp.async.ca.shared.global [%0], [%1], 4;\n" :: "r"(sa), "l"(g));
}
__device__ __forceinline__ void cp_commit() {
    asm volatile("cp.async.commit_group;\n");
}
template <int N>
__device__ __forceinline__ void cp_wait() {
    asm volatile("cp.async.wait_group %0;\n" :: "n"(N));
}

__device__ __forceinline__ uint32_t f2tf(float x) {
    uint32_t u;
    asm("cvt.rna.tf32.f32 %0, %1;" : "=r"(u) : "f"(x));
    return u;
}
__device__ __forceinline__ float round_tf(float x) {
    return __uint_as_float(f2tf(x));
}

__device__ __forceinline__ void mma_tf32(float c[4], const uint32_t a[4],
                                         const uint32_t b[2]) {
    asm volatile(
        "mma.sync.aligned.m16n8k8.row.col.f32.tf32.tf32.f32 "
        "{%0,%1,%2,%3}, {%4,%5,%6,%7}, {%8,%9}, {%0,%1,%2,%3};\n"
        : "+f"(c[0]), "+f"(c[1]), "+f"(c[2]), "+f"(c[3])
        : "r"(a[0]), "r"(a[1]), "r"(a[2]), "r"(a[3]),
          "r"(b[0]), "r"(b[1]));
}

__device__ __forceinline__ float gelu_tanh(float x) {
    float x3 = x * x * x;
    return 0.5f * x * (1.0f + tanhf(0.7978845608028654f * (x + 0.044715f * x3)));
}

// k-pair permutation within a 16-wide k-slab: places k and k+4 adjacent.
__device__ __forceinline__ int kperm(int kk) {
    int blk = kk >> 3, b = kk & 7;
    return (blk << 3) | ((b & 3) << 1) | (b >> 2);
}

// ---------------------------------------------------------------------------
// Tensor-core GEMM: C[Md,Nd] = op(A)[Md,Kd] * B[Kd,Nd] (+bias) (+gelu)
//   TM=128, TN=128, TK=16. 8 warps (2 x 4), warp tile 64x32.
// A smem layout: As[m][16] with k-pair perm + xor swizzle -> LDS.64 fragments.
// remapE>0: row r of A/C maps to global row ((r>>6)*remapE + z)*64 + (r&63)
//   (merges the 4 batches of expert z into M=256 while keeping b-major layout).
// C2 (optional): secondary store of the un-rounded fp32 value (hidden output).
// ---------------------------------------------------------------------------
#define TBM 128
#define TBN 128
#define TBK 16
#define SBS 136

template <bool TRANSA, int ACT, bool SPLIT, bool ACVT, bool BCVT, bool ROUND>
__global__ void __launch_bounds__(256, SPLIT ? 1 : 2) gemm_tc(
    const float* __restrict__ A, const float* __restrict__ B,
    float* __restrict__ C, float* __restrict__ C2,
    const float* __restrict__ bias,
    int Md, int Nd, int Kd,
    long long sA_g, long long sB_g, long long sC_g, long long sBias_g,
    int remapE)
{
    constexpr int MI = 4;  // m16 tiles per warp (warp M = 64)
    constexpr int NI = 4;  // n8 tiles per warp (warp N = 32)

    const int gg = blockIdx.z;
    A += (long long)gg * sA_g;
    B += (long long)gg * sB_g;
    C += (long long)gg * sC_g;
    if (bias) bias += (long long)gg * sBias_g;

    __shared__ float As[2][TBM][16];
    __shared__ float Bs[2][TBK][SBS];

    const int tid  = threadIdx.x;
    const int lane = tid & 31, warp = tid >> 5;
    const int t  = lane & 3;
    const int gq = lane >> 2;
    const int wm = warp & 1, wn = warp >> 1;
    const int m_base = wm * 64;
    const int n_base = wn * 32;
    const int row0 = blockIdx.y * TBM;
    const int col0 = blockIdx.x * TBN;

    auto rowmap = [&](int r) -> long long {
        if (remapE > 0)
            return (long long)((r >> 6) * remapE + gg) * 64 + (r & 63);
        return r;
    };

    auto loadA = [&](int buf, int k0) {
        if (!TRANSA) {
            #pragma unroll
            for (int i = 0; i < (TBM * TBK) / 256; i++) {
                int l = tid + i * 256;
                int kk = l & 15, mm = l >> 4;
                cp_async4(&As[buf][mm][kperm(kk) ^ ((mm & 3) << 2)],
                          &A[rowmap(row0 + mm) * Kd + (k0 + kk)]);
            }
        } else {
            #pragma unroll
            for (int i = 0; i < (TBM * TBK) / 256; i++) {
                int l = tid + i * 256;
                int ii = l & (TBM - 1), kk = l / TBM;
                cp_async4(&As[buf][ii][kperm(kk) ^ ((ii & 3) << 2)],
                          &A[(long long)(k0 + kk) * Md + (row0 + ii)]);
            }
        }
    };
    auto loadB = [&](int buf, int k0) {
        #pragma unroll
        for (int i = 0; i < (TBN * TBK) / 1024; i++) {
            int l = tid * 4 + i * 1024;
            int nn = l % TBN, kk = l / TBN;
            cp_async16(&Bs[buf][kk][nn],
                       &B[(long long)(k0 + kk) * Nd + (col0 + nn)]);
        }
    };

    float acc[MI][NI][4];
    #pragma unroll
    for (int i = 0; i < MI; i++)
        #pragma unroll
        for (int j = 0; j < NI; j++)
            #pragma unroll
            for (int q = 0; q < 4; q++) acc[i][j][q] = 0.0f;

    loadA(0, 0);
    loadB(0, 0);
    cp_commit();

    const int nk = Kd / TBK;
    int buf = 0;
    for (int it = 0; it < nk; it++) {
        if (it + 1 < nk) {
            loadA(buf ^ 1, (it + 1) * TBK);
            loadB(buf ^ 1, (it + 1) * TBK);
            cp_commit();
            cp_wait<1>();
        } else {
            cp_wait<0>();
        }
        __syncthreads();

        #pragma unroll
        for (int ks = 0; ks < TBK; ks += 8) {
            uint32_t Ah[MI][4], Bh[NI][2];
            uint32_t Al[MI][4], Bl[NI][2];

            #pragma unroll
            for (int mi = 0; mi < MI; mi++) {
                const int r = m_base + mi * 16 + gq;
                const int kp = ((2 * t) ^ ((r & 3) << 2)) ^ ks;  // ks in {0,8}
                float2 q0 = *reinterpret_cast<const float2*>(&As[buf][r][kp]);
                float2 q1 = *reinterpret_cast<const float2*>(&As[buf][r + 8][kp]);
                float v[4] = {q0.x, q1.x, q0.y, q1.y};
                #pragma unroll
                for (int q = 0; q < 4; q++) {
                    Ah[mi][q] = (ACVT || SPLIT) ? f2tf(v[q])
                                                : __float_as_uint(v[q]);
                    if (SPLIT)
                        Al[mi][q] = f2tf(v[q] - __uint_as_float(Ah[mi][q]));
                }
            }
            #pragma unroll
            for (int ni = 0; ni < NI; ni++) {
                const int n0 = n_base + ni * 8;
                float u0 = Bs[buf][ks + t    ][n0 + gq];
                float u1 = Bs[buf][ks + t + 4][n0 + gq];
                Bh[ni][0] = (BCVT || SPLIT) ? f2tf(u0) : __float_as_uint(u0);
                Bh[ni][1] = (BCVT || SPLIT) ? f2tf(u1) : __float_as_uint(u1);
                if (SPLIT) {
                    Bl[ni][0] = f2tf(u0 - __uint_as_float(Bh[ni][0]));
                    Bl[ni][1] = f2tf(u1 - __uint_as_float(Bh[ni][1]));
                }
            }

            #pragma unroll
            for (int mi = 0; mi < MI; mi++)
                #pragma unroll
                for (int ni = 0; ni < NI; ni++) {
                    if (SPLIT) {
                        mma_tf32(acc[mi][ni], Ah[mi], Bl[ni]);
                        mma_tf32(acc[mi][ni], Al[mi], Bh[ni]);
                    }
                    mma_tf32(acc[mi][ni], Ah[mi], Bh[ni]);
                }
        }
        __syncthreads();
        buf ^= 1;
    }

    // Epilogue: c0,c1 at (r, 2t/2t+1); c2,c3 at (r+8, same cols)
    #pragma unroll
    for (int mi = 0; mi < MI; mi++) {
        const int r1 = row0 + m_base + mi * 16 + gq;
        const long long ra = rowmap(r1), rb = rowmap(r1 + 8);
        #pragma unroll
        for (int ni = 0; ni < NI; ni++) {
            const int cg = col0 + n_base + ni * 8 + 2 * t;
            float b0 = 0.0f, b1 = 0.0f;
            if (bias) { b0 = bias[cg]; b1 = bias[cg + 1]; }
            float v0 = acc[mi][ni][0] + b0;
            float v1 = acc[mi][ni][1] + b1;
            float v2 = acc[mi][ni][2] + b0;
            float v3 = acc[mi][ni][3] + b1;
            if (ACT == 1) {
                v0 = gelu_tanh(v0); v1 = gelu_tanh(v1);
                v2 = gelu_tanh(v2); v3 = gelu_tanh(v3);
            }
            if (C2) {  // un-rounded fp32 secondary store (hidden output)
                *reinterpret_cast<float2*>(&C2[ra * Nd + cg]) = make_float2(v0, v1);
                *reinterpret_cast<float2*>(&C2[rb * Nd + cg]) = make_float2(v2, v3);
            }
            if (ROUND) {
                v0 = round_tf(v0); v1 = round_tf(v1);
                v2 = round_tf(v2); v3 = round_tf(v3);
            }
            *reinterpret_cast<float2*>(&C[ra * Nd + cg]) = make_float2(v0, v1);
            *reinterpret_cast<float2*>(&C[rb * Nd + cg]) = make_float2(v2, v3);
        }
    }
}

// ---------------------------------------------------------------------------
// x -> tf32-rounded copy
// ---------------------------------------------------------------------------
__global__ __launch_bounds__(256) void round_x_kernel(
    const float4* __restrict__ src, float4* __restrict__ dst, int n4)
{
    int i = blockIdx.x * 256 + threadIdx.x;
    if (i < n4) {
        float4 v = src[i];
        dst[i] = make_float4(round_tf(v.x), round_tf(v.y),
                             round_tf(v.z), round_tf(v.w));
    }
}

// ---------------------------------------------------------------------------
// dispatch = softmax over tokens m (axis 1), output tf32-rounded.
// ---------------------------------------------------------------------------
__global__ __launch_bounds__(256) void dispatch_softmax_kernel(
    const float* __restrict__ logits, float* __restrict__ dispatch)
{
    const int b = blockIdx.y;
    const int ep = blockIdx.x * 32 + threadIdx.x;
    const int tx = threadIdx.x, ty = threadIdx.y;
    const float* base = logits + (long long)b * cM * cEP + ep;
    float* obase = dispatch + (long long)b * cM * cEP + ep;

    float mx = -INFINITY, s = 0.0f;
    for (int m = ty; m < cM; m += 8) {
        float v = base[(long long)m * cEP];
        float nm = fmaxf(mx, v);
        s = s * expf(mx - nm) + expf(v - nm);
        mx = nm;
    }
    __shared__ float smx[8][32], ssum[8][32];
    smx[ty][tx] = mx;
    ssum[ty][tx] = s;
    __syncthreads();
    if (ty == 0) {
        float M_ = smx[0][tx], S = ssum[0][tx];
        #pragma unroll
        for (int i = 1; i < 8; i++) {
            float m2 = smx[i][tx];
            float nm = fmaxf(M_, m2);
            S = S * expf(M_ - nm) + ssum[i][tx] * expf(m2 - nm);
            M_ = nm;
        }
        smx[0][tx] = M_;
        ssum[0][tx] = 1.0f / S;
    }
    __syncthreads();
    const float gmx = smx[0][tx];
    const float inv = ssum[0][tx];
    for (int m = ty; m < cM; m += 8)
        obase[(long long)m * cEP] =
            round_tf(expf(base[(long long)m * cEP] - gmx) * inv);
}

// ---------------------------------------------------------------------------
// combine = softmax over ep (tf32-rounded) + probabilities + argmax (fp32).
// ---------------------------------------------------------------------------
__global__ __launch_bounds__(256) void combine_softmax_kernel(
    const float* __restrict__ logits, float* __restrict__ combine,
    float* __restrict__ prob, float* __restrict__ top)
{
    const long long bm = blockIdx.y * gridDim.x + blockIdx.x;
    const float* row = logits + bm * cEP;
    float* crow = combine + bm * cEP;

    __shared__ float sv[cEP];
    __shared__ float sred[8];
    __shared__ float sbc;
    __shared__ float sprob[cE];

    const int tid = threadIdx.x;
    const int lane = tid & 31, warp = tid >> 5;

    float v[4];
    float mx = -INFINITY;
    #pragma unroll
    for (int i = 0; i < 4; i++) {
        v[i] = row[tid + i * 256];
        mx = fmaxf(mx, v[i]);
    }
    #pragma unroll
    for (int off = 16; off > 0; off >>= 1)
        mx = fmaxf(mx, __shfl_xor_sync(0xffffffffu, mx, off));
    if (lane == 0) sred[warp] = mx;
    __syncthreads();
    if (tid == 0) {
        float m = sred[0];
        #pragma unroll
        for (int i = 1; i < 8; i++) m = fmaxf(m, sred[i]);
        sbc = m;
    }
    __syncthreads();
    const float gmx = sbc;

    float s = 0.0f;
    #pragma unroll
    for (int i = 0; i < 4; i++) {
        float e = expf(v[i] - gmx);
        sv[tid + i * 256] = e;
        s += e;
    }
    #pragma unroll
    for (int off = 16; off > 0; off >>= 1)
        s += __shfl_xor_sync(0xffffffffu, s, off);
    if (lane == 0) sred[warp] = s;
    __syncthreads();
    if (tid == 0) {
        float tt = 0.0f;
        #pragma unroll
        for (int i = 0; i < 8; i++) tt += sred[i];
        sbc = 1.0f / tt;
    }
    __syncthreads();
    const float inv = sbc;

    #pragma unroll
    for (int i = 0; i < 4; i++)
        crow[tid + i * 256] = round_tf(sv[tid + i * 256] * inv);

    #pragma unroll
    for (int e = warp * 2; e < warp * 2 + 2; e++) {
        float s2 = sv[e * 64 + lane] + sv[e * 64 + 32 + lane];
        #pragma unroll
        for (int off = 16; off > 0; off >>= 1)
            s2 += __shfl_xor_sync(0xffffffffu, s2, off);
        if (lane == 0) sprob[e] = s2 * inv * (1.0f / 64.0f);
    }
    __syncthreads();
    if (prob && tid < cE) prob[bm * cE + tid] = sprob[tid];
    if (top && tid == 0) {
        float best = -INFINITY;
        int bi = 0;
        #pragma unroll
        for (int e = 0; e < cE; e++) {
            if (sprob[e] > best) { best = sprob[e]; bi = e; }
        }
        top[bm] = (float)bi;
    }
}

// ---------------------------------------------------------------------------
// Host-side launch
// ---------------------------------------------------------------------------
extern "C" void kernel_launch(void* const* d_in, const int* in_sizes, int n_in,
                              void* d_out, int out_size)
{
    const float* x   = (const float*)d_in[0];  // [B, M, D]
    const float* phi = (const float*)d_in[1];  // [D, EP]
    const float* W1  = (const float*)d_in[2];  // [E, D, F]
    const float* b1  = (const float*)d_in[3];  // [E, F]
    const float* W2  = (const float*)d_in[4];  // [E, F, D]
    const float* b2  = (const float*)d_in[5];  // [E, D]
    float* out = (float*)d_out;

    float *logits, *dispatchp, *combinep, *mixp, *eoutp, *xtf, *hidtf;
    cudaGetSymbolAddress((void**)&logits,    g_logits);
    cudaGetSymbolAddress((void**)&dispatchp, g_dispatch);
    cudaGetSymbolAddress((void**)&combinep,  g_combine);
    cudaGetSymbolAddress((void**)&mixp,      g_mix);
    cudaGetSymbolAddress((void**)&eoutp,     g_eout);
    cudaGetSymbolAddress((void**)&xtf,       g_xtf);
    cudaGetSymbolAddress((void**)&hidtf,     g_hid);

    const bool full = ((long long)out_size >= SZ_FULL);
    float* hid_out = full ? (out + SZ_OUT + SZ_PROB + SZ_TOP) : nullptr;
    float* probp   = full ? (out + SZ_OUT) : nullptr;
    float* topp    = full ? (out + SZ_OUT + SZ_PROB) : nullptr;

    // 0) x -> tf32-rounded copy (B operand of mix)
    {
        int n4 = (cB * cM * cD) / 4;
        round_x_kernel<<<(n4 + 255) / 256, 256>>>(
            (const float4*)x, (float4*)xtf, n4);
    }

    // 1) logits = X[4096,768] @ phi[768,1024]  — 3xTF32 split (fp32-grade)
    gemm_tc<false, 0, true, true, true, false>
        <<<dim3(cEP / TBN, (cB * cM) / TBM, 1), 256>>>(
        x, phi, logits, nullptr, nullptr, cB * cM, cEP, cD,
        0, 0, 0, 0, 0);

    // 2) dispatch = softmax over tokens (tf32-rounded output)
    dispatch_softmax_kernel<<<dim3(cEP / 32, cB), dim3(32, 8)>>>(logits, dispatchp);

    // 3) combine = softmax over (e,p) (rounded) + probabilities + argmax
    combine_softmax_kernel<<<dim3(cM, cB), 256>>>(logits, combinep, probp, topp);

    // 4) mix[b,ep,d] = dispatch[b]^T @ xtf[b]; epilogue rounds to tf32
    gemm_tc<true, 0, false, false, false, true>
        <<<dim3(cD / TBN, cEP / TBM, cB), 256>>>(
        dispatchp, xtf, mixp, nullptr, nullptr, cEP, cD, cM,
        (long long)cM * cEP, (long long)cM * cD, (long long)cEP * cD, 0, 0);

    // 5) hidden = gelu(mix @ W1 + b1); z=expert, M=256 (4 batches merged via
    //    row remap). C = rounded tf32 scratch, C2 = fp32 hidden output.
    gemm_tc<false, 1, false, false, true, true>
        <<<dim3(cF / TBN, (cB * cP) / TBM, cE), 256>>>(
        mixp, W1, hidtf, hid_out, b1, cB * cP, cF, cD,
        0, (long long)cD * cF, 0, (long long)cF, cE);

    // 6) eout = hidden @ W2 + b2; z=expert, M=256; epilogue rounds
    gemm_tc<false, 0, false, false, true, true>
        <<<dim3(cD / TBN, (cB * cP) / TBM, cE), 256>>>(
        hidtf, W2, eoutp, nullptr, b2, cB * cP, cD, cF,
        0, (long long)cF * cD, 0, (long long)cD, cE);

    // 7) outputs = combine[b] @ eout[b]  (both pre-rounded; no cvt)
    gemm_tc<false, 0, false, false, false, false>
        <<<dim3(cD / TBN, cM / TBM, cB), 256>>>(
        combinep, eoutp, out, nullptr, nullptr, cM, cD, cEP,
        (long long)cM * cEP, (long long)cEP * cD, (long long)cM * cD, 0, 0);
}